// round 2
// baseline (speedup 1.0000x reference)
#include <cuda_runtime.h>

// Problem dims
constexpr int Bb   = 2;
constexpr int Tt   = 2048;
constexpr int Dd   = 1024;
constexpr int Hh   = 16;
constexpr int HDim = 64;
constexpr int BT   = Bb * Tt;      // 4096
constexpr int BHn  = Bb * Hh;      // 32
constexpr int CH   = 64;           // chunk length
constexpr int NCH  = Tt / CH;      // 32 chunks per (b,h)

// Scratch (allocation-free: __device__ globals)
__device__ float g_Q[BHn * Tt * HDim];
__device__ float g_K[BHn * Tt * HDim];
__device__ float g_V[BHn * Tt * HDim];
__device__ float g_Y[BHn * Tt * HDim];
__device__ float g_cs[BHn * NCH * HDim * HDim];  // per-chunk K^T V sums
__device__ float g_sp[BHn * NCH * HDim * HDim];  // exclusive prefix states

// ---------------------------------------------------------------------------
// Projection GEMM: out[m,n] = sum_d X[m,d] * W[n,d] + bias[n]
// X: [4096,1024] row-major, W: [1024,1024] row-major (nn.Linear weight).
// Output stored head-major: dst[((b*H + h)*T + t)*64 + hd], n = h*64+hd.
// 128x128 block tile, 8x8 per-thread microtile, BK=16, 256 threads.
// ---------------------------------------------------------------------------
__global__ __launch_bounds__(256) void proj_gemm(const float* __restrict__ X,
                                                 const float* __restrict__ W,
                                                 const float* __restrict__ bias,
                                                 int which)
{
    __shared__ float As[16][128];
    __shared__ float Bs[16][128];
    const int tid = threadIdx.x;
    const int bm = blockIdx.y * 128;
    const int bn = blockIdx.x * 128;
    const int tx = tid & 15;
    const int ty = tid >> 4;
    const int lr = tid >> 2;           // 0..63
    const int lc = (tid & 3) << 2;     // 0,4,8,12

    float acc[8][8];
#pragma unroll
    for (int i = 0; i < 8; i++)
#pragma unroll
        for (int j = 0; j < 8; j++) acc[i][j] = 0.0f;

    const float* Ar0 = X + (size_t)(bm + lr) * Dd + lc;
    const float* Ar1 = Ar0 + (size_t)64 * Dd;
    const float* Br0 = W + (size_t)(bn + lr) * Dd + lc;
    const float* Br1 = Br0 + (size_t)64 * Dd;

    for (int k0 = 0; k0 < Dd; k0 += 16) {
        float4 a0 = *(const float4*)(Ar0 + k0);
        float4 a1 = *(const float4*)(Ar1 + k0);
        float4 b0 = *(const float4*)(Br0 + k0);
        float4 b1 = *(const float4*)(Br1 + k0);
        __syncthreads();
        As[lc + 0][lr] = a0.x; As[lc + 1][lr] = a0.y; As[lc + 2][lr] = a0.z; As[lc + 3][lr] = a0.w;
        As[lc + 0][lr + 64] = a1.x; As[lc + 1][lr + 64] = a1.y; As[lc + 2][lr + 64] = a1.z; As[lc + 3][lr + 64] = a1.w;
        Bs[lc + 0][lr] = b0.x; Bs[lc + 1][lr] = b0.y; Bs[lc + 2][lr] = b0.z; Bs[lc + 3][lr] = b0.w;
        Bs[lc + 0][lr + 64] = b1.x; Bs[lc + 1][lr + 64] = b1.y; Bs[lc + 2][lr + 64] = b1.z; Bs[lc + 3][lr + 64] = b1.w;
        __syncthreads();
#pragma unroll
        for (int k = 0; k < 16; k++) {
            float ra[8], rb[8];
#pragma unroll
            for (int i = 0; i < 8; i++) ra[i] = As[k][ty * 8 + i];
#pragma unroll
            for (int j = 0; j < 8; j++) rb[j] = Bs[k][tx * 8 + j];
#pragma unroll
            for (int i = 0; i < 8; i++)
#pragma unroll
                for (int j = 0; j < 8; j++) acc[i][j] += ra[i] * rb[j];
        }
    }

    float* dst = (which == 0) ? g_Q : (which == 1) ? g_K : g_V;
#pragma unroll
    for (int i = 0; i < 8; i++) {
        int m = bm + ty * 8 + i;
        int b = m >> 11, t = m & 2047;
#pragma unroll
        for (int j = 0; j < 8; j++) {
            int n = bn + tx * 8 + j;
            int h = n >> 6, hd = n & 63;
            dst[(((size_t)(b * Hh + h) * Tt) + t) * HDim + hd] = acc[i][j] + bias[n];
        }
    }
}

// ---------------------------------------------------------------------------
// Output GEMM: out[m,n] = sum_k Y[m,k] * Wo[n,k] + bo[n]; Y gathered from
// head-major layout (k = h*64+hd).
// ---------------------------------------------------------------------------
__global__ __launch_bounds__(256) void out_gemm(const float* __restrict__ W,
                                                const float* __restrict__ bias,
                                                float* __restrict__ out)
{
    __shared__ float As[16][128];
    __shared__ float Bs[16][128];
    const int tid = threadIdx.x;
    const int bm = blockIdx.y * 128;
    const int bn = blockIdx.x * 128;
    const int tx = tid & 15;
    const int ty = tid >> 4;
    const int lr = tid >> 2;
    const int lc = (tid & 3) << 2;

    float acc[8][8];
#pragma unroll
    for (int i = 0; i < 8; i++)
#pragma unroll
        for (int j = 0; j < 8; j++) acc[i][j] = 0.0f;

    const int m0 = bm + lr;
    const int b0 = m0 >> 11, t0 = m0 & 2047;
    const int m1 = m0 + 64;
    const int b1 = m1 >> 11, t1 = m1 & 2047;
    const float* Br0 = W + (size_t)(bn + lr) * Dd + lc;
    const float* Br1 = Br0 + (size_t)64 * Dd;

    for (int k0 = 0; k0 < Dd; k0 += 16) {
        int kk = k0 + lc;
        int h = kk >> 6, hd = kk & 63;
        float4 a0 = *(const float4*)&g_Y[(((size_t)(b0 * Hh + h) * Tt) + t0) * HDim + hd];
        float4 a1 = *(const float4*)&g_Y[(((size_t)(b1 * Hh + h) * Tt) + t1) * HDim + hd];
        float4 b0v = *(const float4*)(Br0 + k0);
        float4 b1v = *(const float4*)(Br1 + k0);
        __syncthreads();
        As[lc + 0][lr] = a0.x; As[lc + 1][lr] = a0.y; As[lc + 2][lr] = a0.z; As[lc + 3][lr] = a0.w;
        As[lc + 0][lr + 64] = a1.x; As[lc + 1][lr + 64] = a1.y; As[lc + 2][lr + 64] = a1.z; As[lc + 3][lr + 64] = a1.w;
        Bs[lc + 0][lr] = b0v.x; Bs[lc + 1][lr] = b0v.y; Bs[lc + 2][lr] = b0v.z; Bs[lc + 3][lr] = b0v.w;
        Bs[lc + 0][lr + 64] = b1v.x; Bs[lc + 1][lr + 64] = b1v.y; Bs[lc + 2][lr + 64] = b1v.z; Bs[lc + 3][lr + 64] = b1v.w;
        __syncthreads();
#pragma unroll
        for (int k = 0; k < 16; k++) {
            float ra[8], rb[8];
#pragma unroll
            for (int i = 0; i < 8; i++) ra[i] = As[k][ty * 8 + i];
#pragma unroll
            for (int j = 0; j < 8; j++) rb[j] = Bs[k][tx * 8 + j];
#pragma unroll
            for (int i = 0; i < 8; i++)
#pragma unroll
                for (int j = 0; j < 8; j++) acc[i][j] += ra[i] * rb[j];
        }
    }

#pragma unroll
    for (int i = 0; i < 8; i++) {
        int m = bm + ty * 8 + i;
#pragma unroll
        for (int j = 0; j < 8; j++) {
            int n = bn + tx * 8 + j;
            out[(size_t)m * Dd + n] = acc[i][j] + bias[n];
        }
    }
}

// ---------------------------------------------------------------------------
// Per-chunk state sums: M[p,n] = sum_{t in chunk} V[t,p] * K[t,n]
// One block per (chunk, bh). 256 threads, 4x4 microtile.
// ---------------------------------------------------------------------------
__global__ __launch_bounds__(256) void chunk_sums()
{
    __shared__ float Ks[64 * 64];
    __shared__ float Vs[64 * 64];
    const int bh = blockIdx.y, c = blockIdx.x;
    const int tid = threadIdx.x;
    const float* Kg = g_K + ((size_t)bh * Tt + c * CH) * HDim;
    const float* Vg = g_V + ((size_t)bh * Tt + c * CH) * HDim;
    for (int i = tid; i < 1024; i += 256) {
        ((float4*)Ks)[i] = ((const float4*)Kg)[i];
        ((float4*)Vs)[i] = ((const float4*)Vg)[i];
    }
    __syncthreads();
    const int tx = tid & 15, ty = tid >> 4;
    float acc[4][4];
#pragma unroll
    for (int i = 0; i < 4; i++)
#pragma unroll
        for (int j = 0; j < 4; j++) acc[i][j] = 0.0f;
#pragma unroll 4
    for (int t = 0; t < 64; t++) {
        float rv[4], rk[4];
#pragma unroll
        for (int i = 0; i < 4; i++) rv[i] = Vs[t * 64 + ty * 4 + i];
#pragma unroll
        for (int j = 0; j < 4; j++) rk[j] = Ks[t * 64 + tx * 4 + j];
#pragma unroll
        for (int i = 0; i < 4; i++)
#pragma unroll
            for (int j = 0; j < 4; j++) acc[i][j] += rv[i] * rk[j];
    }
    float* dst = g_cs + ((size_t)bh * NCH + c) * 4096;
#pragma unroll
    for (int i = 0; i < 4; i++)
#pragma unroll
        for (int j = 0; j < 4; j++)
            dst[(ty * 4 + i) * 64 + tx * 4 + j] = acc[i][j];
}

// ---------------------------------------------------------------------------
// Exclusive prefix over chunks: g_sp[bh,c] = sum_{c' < c} g_cs[bh,c']
// ---------------------------------------------------------------------------
__global__ __launch_bounds__(256) void prefix_kernel()
{
    const int bh = blockIdx.x;
    for (int e = threadIdx.x; e < 4096; e += 256) {
        float acc = 0.0f;
#pragma unroll
        for (int c = 0; c < NCH; c++) {
            size_t off = ((size_t)bh * NCH + c) * 4096 + e;
            g_sp[off] = acc;
            acc += g_cs[off];
        }
    }
}

// ---------------------------------------------------------------------------
// Intra-chunk attention + inter-chunk state term:
// Y[t,p] = sum_{s<=t} (Q[t,:].K[s,:]) V[s,p] + sum_n Q[t,n] Sp[p,n]
// One block per (chunk, bh). Dynamic smem: 5 padded 64x65 tiles = 83200 B.
// ---------------------------------------------------------------------------
extern __shared__ float sm_attn[];
__global__ __launch_bounds__(256) void attn_kernel()
{
    float* Qs = sm_attn;               // [64][65]
    float* Ks = Qs + 64 * 65;
    float* Vs = Ks + 64 * 65;
    float* Sp = Vs + 64 * 65;          // state, rows p, cols n
    float* Am = Sp + 64 * 65;          // masked scores, rows t, cols s
    const int bh = blockIdx.y, c = blockIdx.x;
    const int tid = threadIdx.x;
    const float* Qg = g_Q + ((size_t)bh * Tt + c * CH) * HDim;
    const float* Kg = g_K + ((size_t)bh * Tt + c * CH) * HDim;
    const float* Vg = g_V + ((size_t)bh * Tt + c * CH) * HDim;
    const float* Sg = g_sp + ((size_t)bh * NCH + c) * 4096;

    for (int i = tid; i < 1024; i += 256) {
        int r = i >> 4;               // row 0..63
        int c4 = (i & 15) << 2;       // col 0,4,...,60
        float4 q = *(const float4*)(Qg + r * 64 + c4);
        float4 k = *(const float4*)(Kg + r * 64 + c4);
        float4 v = *(const float4*)(Vg + r * 64 + c4);
        float4 s = *(const float4*)(Sg + r * 64 + c4);
        Qs[r * 65 + c4 + 0] = q.x; Qs[r * 65 + c4 + 1] = q.y; Qs[r * 65 + c4 + 2] = q.z; Qs[r * 65 + c4 + 3] = q.w;
        Ks[r * 65 + c4 + 0] = k.x; Ks[r * 65 + c4 + 1] = k.y; Ks[r * 65 + c4 + 2] = k.z; Ks[r * 65 + c4 + 3] = k.w;
        Vs[r * 65 + c4 + 0] = v.x; Vs[r * 65 + c4 + 1] = v.y; Vs[r * 65 + c4 + 2] = v.z; Vs[r * 65 + c4 + 3] = v.w;
        Sp[r * 65 + c4 + 0] = s.x; Sp[r * 65 + c4 + 1] = s.y; Sp[r * 65 + c4 + 2] = s.z; Sp[r * 65 + c4 + 3] = s.w;
    }
    __syncthreads();

    const int tx = tid & 15, ty = tid >> 4;

    // Phase 1: A[t][s] = (s<=t) ? dot(Q[t],K[s]) : 0
    {
        float a[4][4];
#pragma unroll
        for (int i = 0; i < 4; i++)
#pragma unroll
            for (int j = 0; j < 4; j++) a[i][j] = 0.0f;
#pragma unroll 4
        for (int n = 0; n < 64; n++) {
            float rq[4], rk[4];
#pragma unroll
            for (int i = 0; i < 4; i++) rq[i] = Qs[(ty * 4 + i) * 65 + n];
#pragma unroll
            for (int j = 0; j < 4; j++) rk[j] = Ks[(tx * 4 + j) * 65 + n];
#pragma unroll
            for (int i = 0; i < 4; i++)
#pragma unroll
                for (int j = 0; j < 4; j++) a[i][j] += rq[i] * rk[j];
        }
#pragma unroll
        for (int i = 0; i < 4; i++)
#pragma unroll
            for (int j = 0; j < 4; j++) {
                int t = ty * 4 + i, s = tx * 4 + j;
                Am[t * 65 + s] = (s <= t) ? a[i][j] : 0.0f;
            }
    }
    __syncthreads();

    // Phase 2: Y[t][p] = sum_s Am[t][s] * V[s][p] + sum_n Q[t][n] * Sp[p][n]
    float y[4][4];
#pragma unroll
    for (int i = 0; i < 4; i++)
#pragma unroll
        for (int j = 0; j < 4; j++) y[i][j] = 0.0f;
#pragma unroll 4
    for (int s = 0; s < 64; s++) {
        float ra[4], rv[4];
#pragma unroll
        for (int i = 0; i < 4; i++) ra[i] = Am[(ty * 4 + i) * 65 + s];
#pragma unroll
        for (int j = 0; j < 4; j++) rv[j] = Vs[s * 65 + tx * 4 + j];
#pragma unroll
        for (int i = 0; i < 4; i++)
#pragma unroll
            for (int j = 0; j < 4; j++) y[i][j] += ra[i] * rv[j];
    }
#pragma unroll 4
    for (int n = 0; n < 64; n++) {
        float rq[4], rs[4];
#pragma unroll
        for (int i = 0; i < 4; i++) rq[i] = Qs[(ty * 4 + i) * 65 + n];
#pragma unroll
        for (int j = 0; j < 4; j++) rs[j] = Sp[(tx * 4 + j) * 65 + n];
#pragma unroll
        for (int i = 0; i < 4; i++)
#pragma unroll
            for (int j = 0; j < 4; j++) y[i][j] += rq[i] * rs[j];
    }

    float* Yg = g_Y + ((size_t)bh * Tt + c * CH) * HDim;
#pragma unroll
    for (int i = 0; i < 4; i++)
#pragma unroll
        for (int j = 0; j < 4; j++)
            Yg[(ty * 4 + i) * 64 + tx * 4 + j] = y[i][j];
}

// ---------------------------------------------------------------------------
extern "C" void kernel_launch(void* const* d_in, const int* in_sizes, int n_in,
                              void* d_out, int out_size)
{
    const float* x  = (const float*)d_in[0];
    const float* Wq = (const float*)d_in[1];
    const float* bq = (const float*)d_in[2];
    const float* Wk = (const float*)d_in[3];
    const float* bk = (const float*)d_in[4];
    const float* Wv = (const float*)d_in[5];
    const float* bv = (const float*)d_in[6];
    const float* Wo = (const float*)d_in[7];
    const float* bo = (const float*)d_in[8];
    float* out = (float*)d_out;

    cudaFuncSetAttribute(attn_kernel, cudaFuncAttributeMaxDynamicSharedMemorySize, 5 * 64 * 65 * 4);

    dim3 gproj(Dd / 128, BT / 128);  // (8, 32)
    proj_gemm<<<gproj, 256>>>(x, Wq, bq, 0);
    proj_gemm<<<gproj, 256>>>(x, Wk, bk, 1);
    proj_gemm<<<gproj, 256>>>(x, Wv, bv, 2);
    chunk_sums<<<dim3(NCH, BHn), 256>>>();
    prefix_kernel<<<BHn, 256>>>();
    attn_kernel<<<dim3(NCH, BHn), 256, 5 * 64 * 65 * 4>>>();
    out_gemm<<<gproj, 256>>>(Wo, bo, out);
}

// round 7
// speedup vs baseline: 1.8762x; 1.8762x over previous
#include <cuda_runtime.h>
#include <cstdint>

// ---------------------------------------------------------------- problem dims
constexpr int Bb   = 2;
constexpr int Tt   = 2048;
constexpr int Dd   = 1024;
constexpr int Hh   = 16;
constexpr int HDim = 64;
constexpr int BT   = Bb * Tt;      // 4096
constexpr int BHn  = Bb * Hh;      // 32
constexpr int CH   = 64;           // chunk length (attention)
constexpr int NCH  = Tt / CH;      // 32

// ---------------------------------------------------------------- scratch
__device__ float g_Q[BHn * Tt * HDim];
__device__ float g_K[BHn * Tt * HDim];
__device__ float g_V[BHn * Tt * HDim];
__device__ float g_Y[BHn * Tt * HDim];
__device__ float g_cs[BHn * NCH * HDim * HDim];
__device__ float g_sp[BHn * NCH * HDim * HDim];

extern __shared__ char dyn_smem[];

// ---------------------------------------------------------------- helpers
// pack two floats to bf16x2: low half = lo_val, high half = hi_val
__device__ __forceinline__ uint32_t packbf(float lo_val, float hi_val) {
    uint32_t r;
    asm("cvt.rn.bf16x2.f32 %0, %1, %2;" : "=r"(r) : "f"(hi_val), "f"(lo_val));
    return r;
}

__device__ __forceinline__ void mma_bf16(float* c, const uint32_t* a, const uint32_t* b) {
    asm volatile(
        "mma.sync.aligned.m16n8k16.row.col.f32.bf16.bf16.f32 "
        "{%0,%1,%2,%3}, {%4,%5,%6,%7}, {%8,%9}, {%0,%1,%2,%3};"
        : "+f"(c[0]), "+f"(c[1]), "+f"(c[2]), "+f"(c[3])
        : "r"(a[0]), "r"(a[1]), "r"(a[2]), "r"(a[3]), "r"(b[0]), "r"(b[1]));
}

// ---------------------------------------------------------------- tc_gemm cfg
constexpr int TM = 128, TN = 128, KC = 32;   // CTA tile + K chunk (floats)
constexpr int NKC = Dd / KC;                 // 32
constexpr int PAD_K = 40;                    // bf16 row stride (conflict-free)
constexpr int TILE_B = 128 * PAD_K * 2;      // 10240 bytes per bf16 tile
constexpr int OFF_AHI = 0;
constexpr int OFF_ALO = TILE_B;
constexpr int OFF_BHI = 2 * TILE_B;
constexpr int OFF_BLO = 3 * TILE_B;
constexpr int GEMM_SMEM = 4 * TILE_B;        // 40960 B

// ---------------------------------------------------------------------------
// Tensor-core GEMM via mma.sync (bf16 3-term split, fp32-grade accuracy):
//   out[m,n] = sum_k A[m,k] * W[n,k] + bias[n]
// mode 0/1/2: A = Xsrc row-major, dst = g_Q/g_K/g_V head-major
// mode 3:     A gathered from g_Y head-major, dst = outp row-major
// ---------------------------------------------------------------------------
__global__ __launch_bounds__(256) void tc_gemm(const float* __restrict__ Xsrc,
                                               const float* __restrict__ W,
                                               const float* __restrict__ bias,
                                               float* __restrict__ outp,
                                               int mode)
{
    __shared__ __align__(16) char smem[GEMM_SMEM];
    const int tid  = threadIdx.x;
    const int wid  = tid >> 5;
    const int lane = tid & 31;
    const int bn = blockIdx.x * TN;
    const int bm = blockIdx.y * TM;
    const int m0w = (wid >> 2) * 64;      // warp row offset (2 rows of warps)
    const int n0w = (wid & 3) * 32;       // warp col offset (4 cols of warps)
    const int lrow  = lane >> 2;          // 0..7
    const int lcol2 = (lane & 3) * 2;     // 0,2,4,6

    float c[4][4][4];
#pragma unroll
    for (int mi = 0; mi < 4; mi++)
#pragma unroll
        for (int ni = 0; ni < 4; ni++)
#pragma unroll
            for (int r = 0; r < 4; r++) c[mi][ni][r] = 0.0f;

    float4 pa[4], pb[4];

    // ---- prefetch chunk 0 into registers
    {
        const int k0 = 0;
#pragma unroll
        for (int t = 0; t < 4; t++) {
            int u = tid + t * 256, row = u >> 3, c4 = (u & 7) * 4;
            if (mode < 3) {
                pa[t] = *(const float4*)(Xsrc + (size_t)(bm + row) * Dd + k0 + c4);
            } else {
                int m = bm + row, b = m >> 11, tt = m & 2047;
                int k = k0 + c4, h = k >> 6, hd = k & 63;
                pa[t] = *(const float4*)(g_Y + (((size_t)(b * Hh + h) * Tt) + tt) * HDim + hd);
            }
            pb[t] = *(const float4*)(W + (size_t)(bn + row) * Dd + k0 + c4);
        }
    }

    for (int ck = 0; ck < NKC; ck++) {
        // ---- convert regs -> bf16 hi/lo tiles in smem
#pragma unroll
        for (int t = 0; t < 4; t++) {
            int u = tid + t * 256, row = u >> 3, c4 = (u & 7) * 4;
            int boff = (row * PAD_K + c4) * 2;
            {
                float4 v = pa[t];
                uint32_t h01 = packbf(v.x, v.y);
                uint32_t h23 = packbf(v.z, v.w);
                float lx = v.x - __uint_as_float(h01 << 16);
                float ly = v.y - __uint_as_float(h01 & 0xffff0000u);
                float lz = v.z - __uint_as_float(h23 << 16);
                float lw = v.w - __uint_as_float(h23 & 0xffff0000u);
                *(uint2*)(smem + OFF_AHI + boff) = make_uint2(h01, h23);
                *(uint2*)(smem + OFF_ALO + boff) = make_uint2(packbf(lx, ly), packbf(lz, lw));
            }
            {
                float4 v = pb[t];
                uint32_t h01 = packbf(v.x, v.y);
                uint32_t h23 = packbf(v.z, v.w);
                float lx = v.x - __uint_as_float(h01 << 16);
                float ly = v.y - __uint_as_float(h01 & 0xffff0000u);
                float lz = v.z - __uint_as_float(h23 << 16);
                float lw = v.w - __uint_as_float(h23 & 0xffff0000u);
                *(uint2*)(smem + OFF_BHI + boff) = make_uint2(h01, h23);
                *(uint2*)(smem + OFF_BLO + boff) = make_uint2(packbf(lx, ly), packbf(lz, lw));
            }
        }
        __syncthreads();

        // ---- prefetch next chunk (LDG latency hidden under the MMAs below)
        if (ck + 1 < NKC) {
            const int k0 = (ck + 1) * KC;
#pragma unroll
            for (int t = 0; t < 4; t++) {
                int u = tid + t * 256, row = u >> 3, c4 = (u & 7) * 4;
                if (mode < 3) {
                    pa[t] = *(const float4*)(Xsrc + (size_t)(bm + row) * Dd + k0 + c4);
                } else {
                    int m = bm + row, b = m >> 11, tt = m & 2047;
                    int k = k0 + c4, h = k >> 6, hd = k & 63;
                    pa[t] = *(const float4*)(g_Y + (((size_t)(b * Hh + h) * Tt) + tt) * HDim + hd);
                }
                pb[t] = *(const float4*)(W + (size_t)(bn + row) * Dd + k0 + c4);
            }
        }

        // ---- MMAs over the two k16 steps of this chunk
#pragma unroll
        for (int kk = 0; kk < KC; kk += 16) {
            uint32_t ah[4][4], al[4][4];
#pragma unroll
            for (int mi = 0; mi < 4; mi++) {
                int r0 = m0w + mi * 16 + lrow;
                int o00 = (r0 * PAD_K + kk + lcol2) * 2;
                int o10 = ((r0 + 8) * PAD_K + kk + lcol2) * 2;
                ah[mi][0] = *(const uint32_t*)(smem + OFF_AHI + o00);
                ah[mi][1] = *(const uint32_t*)(smem + OFF_AHI + o10);
                ah[mi][2] = *(const uint32_t*)(smem + OFF_AHI + o00 + 16);
                ah[mi][3] = *(const uint32_t*)(smem + OFF_AHI + o10 + 16);
                al[mi][0] = *(const uint32_t*)(smem + OFF_ALO + o00);
                al[mi][1] = *(const uint32_t*)(smem + OFF_ALO + o10);
                al[mi][2] = *(const uint32_t*)(smem + OFF_ALO + o00 + 16);
                al[mi][3] = *(const uint32_t*)(smem + OFF_ALO + o10 + 16);
            }
            uint32_t bh[4][2], bl[4][2];
#pragma unroll
            for (int ni = 0; ni < 4; ni++) {
                int nr = n0w + ni * 8 + lrow;
                int o = (nr * PAD_K + kk + lcol2) * 2;
                bh[ni][0] = *(const uint32_t*)(smem + OFF_BHI + o);
                bh[ni][1] = *(const uint32_t*)(smem + OFF_BHI + o + 16);
                bl[ni][0] = *(const uint32_t*)(smem + OFF_BLO + o);
                bl[ni][1] = *(const uint32_t*)(smem + OFF_BLO + o + 16);
            }
#pragma unroll
            for (int mi = 0; mi < 4; mi++)
#pragma unroll
                for (int ni = 0; ni < 4; ni++) {
                    mma_bf16(c[mi][ni], ah[mi], bh[ni]);   // Ah*Bh
                    mma_bf16(c[mi][ni], ah[mi], bl[ni]);   // Ah*Bl
                    mma_bf16(c[mi][ni], al[mi], bh[ni]);   // Al*Bh
                }
        }
        __syncthreads();
    }

    // ---- epilogue
#pragma unroll
    for (int mi = 0; mi < 4; mi++) {
        int row0 = bm + m0w + mi * 16 + lrow;
        int row1 = row0 + 8;
#pragma unroll
        for (int ni = 0; ni < 4; ni++) {
            int n = bn + n0w + ni * 8 + lcol2;
            float b0 = bias[n], b1 = bias[n + 1];
            float2 v0 = make_float2(c[mi][ni][0] + b0, c[mi][ni][1] + b1);
            float2 v1 = make_float2(c[mi][ni][2] + b0, c[mi][ni][3] + b1);
            if (mode < 3) {
                float* base = (mode == 0) ? g_Q : (mode == 1) ? g_K : g_V;
                int h = n >> 6, hd = n & 63;
                int bb0 = row0 >> 11, t0 = row0 & 2047;
                int bb1 = row1 >> 11, t1 = row1 & 2047;
                *(float2*)(base + (((size_t)(bb0 * Hh + h) * Tt) + t0) * HDim + hd) = v0;
                *(float2*)(base + (((size_t)(bb1 * Hh + h) * Tt) + t1) * HDim + hd) = v1;
            } else {
                *(float2*)(outp + (size_t)row0 * Dd + n) = v0;
                *(float2*)(outp + (size_t)row1 * Dd + n) = v1;
            }
        }
    }
}

// ---------------------------------------------------------------------------
// Per-chunk state sums: M[p,n] = sum_{t in chunk} V[t,p] * K[t,n]
// ---------------------------------------------------------------------------
__global__ __launch_bounds__(256) void chunk_sums()
{
    __shared__ float Ks[64 * 64];
    __shared__ float Vs[64 * 64];
    const int bh = blockIdx.y, c = blockIdx.x;
    const int tid = threadIdx.x;
    const float* Kg = g_K + ((size_t)bh * Tt + c * CH) * HDim;
    const float* Vg = g_V + ((size_t)bh * Tt + c * CH) * HDim;
    for (int i = tid; i < 1024; i += 256) {
        ((float4*)Ks)[i] = ((const float4*)Kg)[i];
        ((float4*)Vs)[i] = ((const float4*)Vg)[i];
    }
    __syncthreads();
    const int tx = tid & 15, ty = tid >> 4;
    float acc[4][4];
#pragma unroll
    for (int i = 0; i < 4; i++)
#pragma unroll
        for (int j = 0; j < 4; j++) acc[i][j] = 0.0f;
#pragma unroll 4
    for (int t = 0; t < 64; t++) {
        float rv[4], rk[4];
#pragma unroll
        for (int i = 0; i < 4; i++) rv[i] = Vs[t * 64 + ty * 4 + i];
#pragma unroll
        for (int j = 0; j < 4; j++) rk[j] = Ks[t * 64 + tx * 4 + j];
#pragma unroll
        for (int i = 0; i < 4; i++)
#pragma unroll
            for (int j = 0; j < 4; j++) acc[i][j] += rv[i] * rk[j];
    }
    float* dst = g_cs + ((size_t)bh * NCH + c) * 4096;
#pragma unroll
    for (int i = 0; i < 4; i++)
#pragma unroll
        for (int j = 0; j < 4; j++)
            dst[(ty * 4 + i) * 64 + tx * 4 + j] = acc[i][j];
}

// ---------------------------------------------------------------------------
// Exclusive prefix over chunks
// ---------------------------------------------------------------------------
__global__ __launch_bounds__(256) void prefix_kernel()
{
    const int bh = blockIdx.x;
    for (int e = threadIdx.x; e < 4096; e += 256) {
        float acc = 0.0f;
#pragma unroll
        for (int c = 0; c < NCH; c++) {
            size_t off = ((size_t)bh * NCH + c) * 4096 + e;
            g_sp[off] = acc;
            acc += g_cs[off];
        }
    }
}

// ---------------------------------------------------------------------------
// Intra-chunk attention + inter-chunk state term
// ---------------------------------------------------------------------------
__global__ __launch_bounds__(256) void attn_kernel()
{
    float* Qs = (float*)dyn_smem;      // [64][65]
    float* Ks = Qs + 64 * 65;
    float* Vs = Ks + 64 * 65;
    float* Sp = Vs + 64 * 65;
    float* Am = Sp + 64 * 65;
    const int bh = blockIdx.y, c = blockIdx.x;
    const int tid = threadIdx.x;
    const float* Qg = g_Q + ((size_t)bh * Tt + c * CH) * HDim;
    const float* Kg = g_K + ((size_t)bh * Tt + c * CH) * HDim;
    const float* Vg = g_V + ((size_t)bh * Tt + c * CH) * HDim;
    const float* Sg = g_sp + ((size_t)bh * NCH + c) * 4096;

    for (int i = tid; i < 1024; i += 256) {
        int r = i >> 4;
        int c4 = (i & 15) << 2;
        float4 q = *(const float4*)(Qg + r * 64 + c4);
        float4 k = *(const float4*)(Kg + r * 64 + c4);
        float4 v = *(const float4*)(Vg + r * 64 + c4);
        float4 s = *(const float4*)(Sg + r * 64 + c4);
        Qs[r * 65 + c4 + 0] = q.x; Qs[r * 65 + c4 + 1] = q.y; Qs[r * 65 + c4 + 2] = q.z; Qs[r * 65 + c4 + 3] = q.w;
        Ks[r * 65 + c4 + 0] = k.x; Ks[r * 65 + c4 + 1] = k.y; Ks[r * 65 + c4 + 2] = k.z; Ks[r * 65 + c4 + 3] = k.w;
        Vs[r * 65 + c4 + 0] = v.x; Vs[r * 65 + c4 + 1] = v.y; Vs[r * 65 + c4 + 2] = v.z; Vs[r * 65 + c4 + 3] = v.w;
        Sp[r * 65 + c4 + 0] = s.x; Sp[r * 65 + c4 + 1] = s.y; Sp[r * 65 + c4 + 2] = s.z; Sp[r * 65 + c4 + 3] = s.w;
    }
    __syncthreads();

    const int tx = tid & 15, ty = tid >> 4;

    {
        float a[4][4];
#pragma unroll
        for (int i = 0; i < 4; i++)
#pragma unroll
            for (int j = 0; j < 4; j++) a[i][j] = 0.0f;
#pragma unroll 4
        for (int n = 0; n < 64; n++) {
            float rq[4], rk[4];
#pragma unroll
            for (int i = 0; i < 4; i++) rq[i] = Qs[(ty * 4 + i) * 65 + n];
#pragma unroll
            for (int j = 0; j < 4; j++) rk[j] = Ks[(tx * 4 + j) * 65 + n];
#pragma unroll
            for (int i = 0; i < 4; i++)
#pragma unroll
                for (int j = 0; j < 4; j++) a[i][j] += rq[i] * rk[j];
        }
#pragma unroll
        for (int i = 0; i < 4; i++)
#pragma unroll
            for (int j = 0; j < 4; j++) {
                int t = ty * 4 + i, s = tx * 4 + j;
                Am[t * 65 + s] = (s <= t) ? a[i][j] : 0.0f;
            }
    }
    __syncthreads();

    float y[4][4];
#pragma unroll
    for (int i = 0; i < 4; i++)
#pragma unroll
        for (int j = 0; j < 4; j++) y[i][j] = 0.0f;
#pragma unroll 4
    for (int s = 0; s < 64; s++) {
        float ra[4], rv[4];
#pragma unroll
        for (int i = 0; i < 4; i++) ra[i] = Am[(ty * 4 + i) * 65 + s];
#pragma unroll
        for (int j = 0; j < 4; j++) rv[j] = Vs[s * 65 + tx * 4 + j];
#pragma unroll
        for (int i = 0; i < 4; i++)
#pragma unroll
            for (int j = 0; j < 4; j++) y[i][j] += ra[i] * rv[j];
    }
#pragma unroll 4
    for (int n = 0; n < 64; n++) {
        float rq[4], rs[4];
#pragma unroll
        for (int i = 0; i < 4; i++) rq[i] = Qs[(ty * 4 + i) * 65 + n];
#pragma unroll
        for (int j = 0; j < 4; j++) rs[j] = Sp[(tx * 4 + j) * 65 + n];
#pragma unroll
        for (int i = 0; i < 4; i++)
#pragma unroll
            for (int j = 0; j < 4; j++) y[i][j] += rq[i] * rs[j];
    }

    float* Yg = g_Y + ((size_t)bh * Tt + c * CH) * HDim;
#pragma unroll
    for (int i = 0; i < 4; i++)
#pragma unroll
        for (int j = 0; j < 4; j++)
            Yg[(ty * 4 + i) * 64 + tx * 4 + j] = y[i][j];
}

// ---------------------------------------------------------------------------
extern "C" void kernel_launch(void* const* d_in, const int* in_sizes, int n_in,
                              void* d_out, int out_size)
{
    const float* x  = (const float*)d_in[0];
    const float* Wq = (const float*)d_in[1];
    const float* bq = (const float*)d_in[2];
    const float* Wk = (const float*)d_in[3];
    const float* bk = (const float*)d_in[4];
    const float* Wv = (const float*)d_in[5];
    const float* bv = (const float*)d_in[6];
    const float* Wo = (const float*)d_in[7];
    const float* bo = (const float*)d_in[8];
    float* out = (float*)d_out;

    cudaFuncSetAttribute(attn_kernel, cudaFuncAttributeMaxDynamicSharedMemorySize, 5 * 64 * 65 * 4);

    dim3 gproj(Dd / TN, BT / TM);  // (8, 32)
    tc_gemm<<<gproj, 256>>>(x, Wq, bq, nullptr, 0);
    tc_gemm<<<gproj, 256>>>(x, Wk, bk, nullptr, 1);
    tc_gemm<<<gproj, 256>>>(x, Wv, bv, nullptr, 2);
    chunk_sums<<<dim3(NCH, BHn), 256>>>();
    prefix_kernel<<<BHn, 256>>>();
    attn_kernel<<<dim3(NCH, BHn), 256, 5 * 64 * 65 * 4>>>();
    tc_gemm<<<gproj, 256>>>(nullptr, Wo, bo, out, 3);
}